// round 2
// baseline (speedup 1.0000x reference)
#include <cuda_runtime.h>

#define B 8
#define N 2048
#define D 128
#define TI 64
#define TJ 64
#define DP 129               // padded row stride (floats) -> conflict-free LDS
#define TEMP (1.0f / 13.544f)

// scratch (allocation-free rule: __device__ globals)
__device__ float g_sq[B * N];
__device__ float g_rowsum[B * N];

// ---------------------------------------------------------------------------
// Kernel 0: per-row squared norms. One warp per row (128 floats = 4/lane).
// ---------------------------------------------------------------------------
__global__ void sq_kernel(const float* __restrict__ x) {
    int row = blockIdx.x * (blockDim.x >> 5) + (threadIdx.x >> 5);
    int lane = threadIdx.x & 31;
    if (row >= B * N) return;
    float4 v = reinterpret_cast<const float4*>(x + (size_t)row * D)[lane];
    float s = v.x * v.x + v.y * v.y + v.z * v.z + v.w * v.w;
    #pragma unroll
    for (int o = 16; o; o >>= 1) s += __shfl_xor_sync(0xffffffffu, s, o);
    if (lane == 0) g_sq[row] = s;
}

// ---------------------------------------------------------------------------
// Kernel 1: per (batch, 64-row tile): sweep all 2048 columns.
//   dot tile 64x64 via 4x4 register tiling (16x16 threads),
//   dist = sq_i - 2*dot + sq_j (clamped), p = exp(-T*dist),
//   write unnormalized p to out, accumulate exact row sums.
// Column/row assignment is strided by 16 so LDS within a warp is
// conflict-free (DP=129 => bank stride 1 across the 16 tx lanes).
// ---------------------------------------------------------------------------
extern __shared__ float smem[];

__global__ void __launch_bounds__(256, 2)
sim_kernel(const float* __restrict__ x, float* __restrict__ out) {
    const int b = blockIdx.y;
    const int i0 = blockIdx.x * TI;

    float* Xi  = smem;                 // TI * DP
    float* Xj  = smem + TI * DP;       // TJ * DP
    float* sqi = Xj + TJ * DP;         // TI
    float* sqj = sqi + TI;             // TJ

    const int tid = threadIdx.x;
    const int tx = tid & 15;
    const int ty = tid >> 4;

    const float* xb = x + (size_t)b * N * D;

    // load Xi tile (coalesced float4 reads, padded smem rows)
    for (int idx = tid; idx < TI * (D / 4); idx += 256) {
        int r  = idx >> 5;        // D/4 == 32
        int k4 = idx & 31;
        float4 v = reinterpret_cast<const float4*>(xb + (size_t)(i0 + r) * D)[k4];
        float* dst = Xi + r * DP + k4 * 4;
        dst[0] = v.x; dst[1] = v.y; dst[2] = v.z; dst[3] = v.w;
    }
    if (tid < TI) sqi[tid] = g_sq[b * N + i0 + tid];

    float rsum[4] = {0.f, 0.f, 0.f, 0.f};

    for (int j0 = 0; j0 < N; j0 += TJ) {
        __syncthreads();   // previous tile's compute done before overwriting Xj
        for (int idx = tid; idx < TJ * (D / 4); idx += 256) {
            int r  = idx >> 5;
            int k4 = idx & 31;
            float4 v = reinterpret_cast<const float4*>(xb + (size_t)(j0 + r) * D)[k4];
            float* dst = Xj + r * DP + k4 * 4;
            dst[0] = v.x; dst[1] = v.y; dst[2] = v.z; dst[3] = v.w;
        }
        if (tid < TJ) sqj[tid] = g_sq[b * N + j0 + tid];
        __syncthreads();

        float acc[4][4];
        #pragma unroll
        for (int ci = 0; ci < 4; ci++)
            #pragma unroll
            for (int cj = 0; cj < 4; cj++) acc[ci][cj] = 0.f;

        #pragma unroll 8
        for (int k = 0; k < D; k++) {
            float a[4], bb[4];
            #pragma unroll
            for (int c = 0; c < 4; c++) a[c]  = Xi[(ty + 16 * c) * DP + k];
            #pragma unroll
            for (int c = 0; c < 4; c++) bb[c] = Xj[(tx + 16 * c) * DP + k];
            #pragma unroll
            for (int ci = 0; ci < 4; ci++)
                #pragma unroll
                for (int cj = 0; cj < 4; cj++)
                    acc[ci][cj] = fmaf(a[ci], bb[cj], acc[ci][cj]);
        }

        // epilogue: dist -> exp -> store + rowsum
        float si[4], sj[4];
        #pragma unroll
        for (int c = 0; c < 4; c++) si[c] = sqi[ty + 16 * c];
        #pragma unroll
        for (int c = 0; c < 4; c++) sj[c] = sqj[tx + 16 * c];

        #pragma unroll
        for (int ci = 0; ci < 4; ci++) {
            int irow = i0 + ty + 16 * ci;
            float* orow = out + ((size_t)(b * N + irow)) * N + j0;
            #pragma unroll
            for (int cj = 0; cj < 4; cj++) {
                float dist = si[ci] - 2.0f * acc[ci][cj] + sj[cj];
                dist = fmaxf(dist, 0.0f);
                float p = __expf(-TEMP * dist);
                rsum[ci] += p;
                orow[tx + 16 * cj] = p;
            }
        }
    }

    // row sums: reduce across the 16 tx lanes (same ty half of the warp)
    #pragma unroll
    for (int ci = 0; ci < 4; ci++) {
        float v = rsum[ci];
        #pragma unroll
        for (int o = 1; o < 16; o <<= 1) v += __shfl_xor_sync(0xffffffffu, v, o);
        if (tx == 0) g_rowsum[b * N + i0 + ty + 16 * ci] = v;
    }
}

// ---------------------------------------------------------------------------
// Kernel 2: normalize out by its row sum (float4 grid-stride).
// ---------------------------------------------------------------------------
__global__ void norm_kernel(float* __restrict__ out) {
    int idx = blockIdx.x * blockDim.x + threadIdx.x;        // one float4 each
    const int total4 = B * N * N / 4;
    if (idx >= total4) return;
    int row = idx >> 9;                                     // N/4 = 512 float4/row
    float inv = __fdividef(1.0f, g_rowsum[row]);
    float4 v = reinterpret_cast<float4*>(out)[idx];
    v.x *= inv; v.y *= inv; v.z *= inv; v.w *= inv;
    reinterpret_cast<float4*>(out)[idx] = v;
}

// ---------------------------------------------------------------------------
extern "C" void kernel_launch(void* const* d_in, const int* in_sizes, int n_in,
                              void* d_out, int out_size) {
    const float* x = (const float*)d_in[0];
    float* out = (float*)d_out;

    // rows' squared norms
    sq_kernel<<<(B * N) / 8, 256>>>(x);

    // main similarity sweep
    size_t smem_bytes = (size_t)(TI * DP + TJ * DP + TI + TJ) * sizeof(float);
    cudaFuncSetAttribute(sim_kernel, cudaFuncAttributeMaxDynamicSharedMemorySize,
                         (int)smem_bytes);
    dim3 grid(N / TI, B);
    sim_kernel<<<grid, 256, smem_bytes>>>(x, out);

    // normalize
    int total4 = B * N * N / 4;
    norm_kernel<<<(total4 + 255) / 256, 256>>>(out);
}